// round 13
// baseline (speedup 1.0000x reference)
#include <cuda_runtime.h>
#include <cuda_fp16.h>
#include <math.h>
#include <stdint.h>

#define EMBED 1024
#define HEADS 16
#define HD 64
#define MLP_DIM 4096
#define BATCH 8
#define SEQ 1024
#define ROWS (BATCH * SEQ)   // 8192

// ---------------- scratch (device globals: no allocation allowed) -----------
__device__ __half g_h[ROWS * EMBED];          // 16 MB (LN outputs, fp16)
__device__ __half g_qkv[ROWS * 3 * EMBED];    // 50 MB (fp16, Q pre-scaled)
__device__ __half g_attn[ROWS * EMBED];       // 16 MB (fp16)
__device__ __half g_fc1[ROWS * MLP_DIM];      // 64 MB (fp16)
__device__ __half g_wt[12582912];             // 24 MB (transposed weights, fp16)

#define WT_QKV  0
#define WT_PROJ (3 * EMBED * EMBED)
#define WT_FC1  (WT_PROJ + EMBED * EMBED)
#define WT_FC2  (WT_FC1 + EMBED * MLP_DIM)

__device__ __forceinline__ void cp16(uint32_t dst, const void* src) {
    asm volatile("cp.async.cg.shared.global [%0], [%1], 16;"
                 :: "r"(dst), "l"(src) : "memory");
}
#define CP_COMMIT() asm volatile("cp.async.commit_group;" ::: "memory")
#define CP_WAIT(n)  asm volatile("cp.async.wait_group %0;" :: "n"(n) : "memory")

#define LDSM4(r0, r1, r2, r3, addr) \
    asm volatile("ldmatrix.sync.aligned.m8n8.x4.shared.b16 {%0,%1,%2,%3}, [%4];" \
                 : "=r"(r0), "=r"(r1), "=r"(r2), "=r"(r3) : "r"(addr))
#define LDSM4T(r0, r1, r2, r3, addr) \
    asm volatile("ldmatrix.sync.aligned.m8n8.x4.trans.shared.b16 {%0,%1,%2,%3}, [%4];" \
                 : "=r"(r0), "=r"(r1), "=r"(r2), "=r"(r3) : "r"(addr))

#define HMMA(d, a0, a1, a2, a3, b0, b1) \
    asm volatile("mma.sync.aligned.m16n8k16.row.col.f32.f16.f16.f32 " \
                 "{%0,%1,%2,%3}, {%4,%5,%6,%7}, {%8,%9}, {%0,%1,%2,%3};" \
                 : "+f"((d)[0]), "+f"((d)[1]), "+f"((d)[2]), "+f"((d)[3]) \
                 : "r"(a0), "r"(a1), "r"(a2), "r"(a3), "r"(b0), "r"(b1))

__device__ __forceinline__ uint32_t pack2(float x, float y) {
    __half2 h = __floats2half2_rn(x, y);
    return *reinterpret_cast<uint32_t*>(&h);
}

// ---------------- weight transpose: out[N,K] = fp16(in[K,N]^T) --------------
__global__ __launch_bounds__(256) void transpose_kernel(
    const float* __restrict__ in, __half* __restrict__ out, int K, int N)
{
    __shared__ float tile[32][33];
    int n0 = blockIdx.x * 32, k0 = blockIdx.y * 32;
    int tx = threadIdx.x, ty = threadIdx.y;   // 32 x 8
    #pragma unroll
    for (int i = 0; i < 32; i += 8)
        tile[ty + i][tx] = in[(size_t)(k0 + ty + i) * N + n0 + tx];
    __syncthreads();
    #pragma unroll
    for (int i = 0; i < 32; i += 8)
        out[(size_t)(n0 + ty + i) * K + k0 + tx] = __float2half_rn(tile[tx][ty + i]);
}

// ---------------- fp16 mma.sync GEMM: C = A[M,K] @ WT[N,K]^T ----------------
// CTA 128x128, 4 warps (2M x 2N), warp tile 64x64, m16n8k16 atoms.
// BK=32, 4-stage cp.async pipeline, ONE __syncthreads per slab, loads issued
// before compute each slab.
// MODE 0: +bias -> f32 | MODE 1: +bias+res -> f32 | MODE 2: +bias,GELU -> f16
// MODE 3: +bias -> f16 | MODE 4: +bias, cols<EMBED x0.125 -> f16 (QKV)
#define ROWH   40
#define TILE_B (128 * ROWH * 2)            // 10240 bytes per operand tile
#define NSTAGE 4
#define TGEMM_SMEM (NSTAGE * 2 * TILE_B)   // 81920 bytes

template <int MODE>
__global__ __launch_bounds__(128, 2) void tgemm(
    const __half* __restrict__ A, const __half* __restrict__ WT,
    const float* __restrict__ bias, const float* __restrict__ res,
    void* __restrict__ Cv, int N, int K)
{
    extern __shared__ char smc[];
    const uint32_t smb = (uint32_t)__cvta_generic_to_shared(smc);
    const int t = threadIdx.x;
    const int warp = t >> 5, lane = t & 31;
    const int lr = lane >> 2, lc = lane & 3;
    const int wm = warp >> 1, wn = warp & 1;     // 2 x 2
    const int m0 = blockIdx.y << 7;
    const int n0 = blockIdx.x << 7;

    float acc[4][8][4];
    #pragma unroll
    for (int m = 0; m < 4; m++)
        #pragma unroll
        for (int n = 0; n < 8; n++)
            #pragma unroll
            for (int r = 0; r < 4; r++) acc[m][n][r] = 0.f;

    const __half* Ab = A  + (size_t)m0 * K;
    const __half* Bb = WT + (size_t)n0 * K;
    const int S = K >> 5;

    const int lrow  = t >> 2;    // 0..31
    const int lpart = t & 3;

    const int rA  = lane & 15;
    const int khA = (lane >> 4) << 3;
    const int rB  = (lane & 7) + ((lane >> 4) << 3);
    const int khB = ((lane >> 3) & 1) << 3;

    #define STAGE_LOAD(buf, kc)                                                  \
        do {                                                                     \
            uint32_t sa = smb + (uint32_t)(buf) * (2 * TILE_B);                  \
            uint32_t sb = sa + TILE_B;                                           \
            _Pragma("unroll")                                                    \
            for (int i = 0; i < 4; i++) {                                        \
                int rw = lrow + 32 * i;                                          \
                cp16(sa + rw * 80 + lpart * 16,                                  \
                     Ab + (size_t)rw * K + (kc) + lpart * 8);                    \
                cp16(sb + rw * 80 + lpart * 16,                                  \
                     Bb + (size_t)rw * K + (kc) + lpart * 8);                    \
            }                                                                    \
        } while (0)

    STAGE_LOAD(0, 0);
    CP_COMMIT();
    if (S > 1) { STAGE_LOAD(1, 32); CP_COMMIT(); }
    if (S > 2) { STAGE_LOAD(2, 64); CP_COMMIT(); }

    int buf = 0;
    for (int s = 0; s < S; s++) {
        if (s + 2 < S)      { CP_WAIT(2); }
        else if (s + 1 < S) { CP_WAIT(1); }
        else                { CP_WAIT(0); }
        __syncthreads();

        // Issue next stage load FIRST (target buf+3 == buf-1 mod 4: all reads
        // of it finished before the barrier above), then compute.
        if (s + 3 < S) {
            int nb = buf + 3; if (nb >= NSTAGE) nb -= NSTAGE;
            STAGE_LOAD(nb, (s + 3) << 5);
            CP_COMMIT();
        }

        const uint32_t As = smb + (uint32_t)buf * (2 * TILE_B);
        const uint32_t Bs = As + TILE_B;
        #pragma unroll
        for (int kk = 0; kk < 2; kk++) {
            uint32_t a[4][4], b[8][2];
            #pragma unroll
            for (int m = 0; m < 4; m++) {
                uint32_t addr = As + (uint32_t)(wm * 64 + m * 16 + rA) * 80u
                              + (uint32_t)(kk * 16 + khA) * 2u;
                LDSM4(a[m][0], a[m][1], a[m][2], a[m][3], addr);
            }
            #pragma unroll
            for (int np = 0; np < 4; np++) {
                uint32_t addr = Bs + (uint32_t)(wn * 64 + np * 16 + rB) * 80u
                              + (uint32_t)(kk * 16 + khB) * 2u;
                LDSM4(b[2 * np][0], b[2 * np][1], b[2 * np + 1][0], b[2 * np + 1][1], addr);
            }
            #pragma unroll
            for (int m = 0; m < 4; m++)
                #pragma unroll
                for (int n = 0; n < 8; n++)
                    HMMA(acc[m][n], a[m][0], a[m][1], a[m][2], a[m][3],
                         b[n][0], b[n][1]);
        }
        buf = buf + 1; if (buf == NSTAGE) buf = 0;
    }
    #undef STAGE_LOAD

    // ---------------- epilogue ----------------
    const int rb = m0 + wm * 64;
    const int cb = n0 + wn * 64;
    #pragma unroll
    for (int m = 0; m < 4; m++) {
        #pragma unroll
        for (int n = 0; n < 8; n++) {
            int r = rb + m * 16 + lr;
            int c = cb + n * 8 + lc * 2;
            float2 bv = *reinterpret_cast<const float2*>(bias + c);
            #pragma unroll
            for (int half_ = 0; half_ < 2; half_++) {
                int rr = r + half_ * 8;
                float o0 = acc[m][n][2 * half_ + 0] + bv.x;
                float o1 = acc[m][n][2 * half_ + 1] + bv.y;
                size_t off = (size_t)rr * N + c;
                if (MODE == 1) {
                    float2 rv = *reinterpret_cast<const float2*>(res + off);
                    o0 += rv.x; o1 += rv.y;
                }
                if (MODE == 2) {
                    o0 = 0.5f * o0 * (1.0f + erff(o0 * 0.70710678118654752f));
                    o1 = 0.5f * o1 * (1.0f + erff(o1 * 0.70710678118654752f));
                }
                if (MODE == 4) {
                    // Q columns (global col < EMBED) pre-scaled by 1/sqrt(hd)
                    float sc = (c < EMBED) ? 0.125f : 1.0f;
                    o0 *= sc; o1 *= sc;
                }
                if (MODE >= 2) {
                    *reinterpret_cast<__half2*>((__half*)Cv + off) =
                        __floats2half2_rn(o0, o1);
                } else {
                    *reinterpret_cast<float2*>((float*)Cv + off) = make_float2(o0, o1);
                }
            }
        }
    }
}

// ---------------- LayerNorm: one block per row (fp16 output) ----------------
__global__ __launch_bounds__(256) void ln_kernel(
    const float* __restrict__ x, const float* __restrict__ g,
    const float* __restrict__ b, __half* __restrict__ out)
{
    int row = blockIdx.x;
    int t = threadIdx.x;
    const float4* xr = reinterpret_cast<const float4*>(x + (size_t)row * EMBED);
    float4 v = xr[t];
    float s  = v.x + v.y + v.z + v.w;
    float ss = v.x * v.x + v.y * v.y + v.z * v.z + v.w * v.w;
    #pragma unroll
    for (int o = 16; o > 0; o >>= 1) {
        s  += __shfl_xor_sync(0xffffffffu, s,  o);
        ss += __shfl_xor_sync(0xffffffffu, ss, o);
    }
    __shared__ float sm[8], sm2[8];
    int w = t >> 5, l = t & 31;
    if (l == 0) { sm[w] = s; sm2[w] = ss; }
    __syncthreads();
    float tot = 0.f, tot2 = 0.f;
    #pragma unroll
    for (int i = 0; i < 8; i++) { tot += sm[i]; tot2 += sm2[i]; }
    float mu   = tot * (1.0f / EMBED);
    float var  = tot2 * (1.0f / EMBED) - mu * mu;
    float rstd = rsqrtf(var + 1e-5f);
    float4 gg = reinterpret_cast<const float4*>(g)[t];
    float4 bb = reinterpret_cast<const float4*>(b)[t];
    __half2* op = reinterpret_cast<__half2*>(out + (size_t)row * EMBED);
    op[2 * t + 0] = __floats2half2_rn((v.x - mu) * rstd * gg.x + bb.x,
                                      (v.y - mu) * rstd * gg.y + bb.y);
    op[2 * t + 1] = __floats2half2_rn((v.z - mu) * rstd * gg.z + bb.z,
                                      (v.w - mu) * rstd * gg.w + bb.w);
}

// ---------------- Flash attention, fp16 tensor cores, Q-tile 128 ------------
// grid (B*H, SEQ/128), 256 threads (8 warps x 16 Q rows). KV tiles of 64,
// double-buffered cp.async; Q is pre-scaled by 0.125 in the QKV epilogue.
#define FPITCH 72                 // halves per smem row
#define FP_B   (FPITCH * 2)       // 144 bytes
#define FKV_B  (64 * FP_B)        // 9216 bytes per K or V tile
#define FLASH_SMEM (128 * FP_B + 4 * FKV_B)   // 18432 + 36864 = 55296

__global__ __launch_bounds__(256, 2) void flash_mma(
    const __half* __restrict__ qkv, __half* __restrict__ out)
{
    extern __shared__ __half fsm[];
    const uint32_t qsm = (uint32_t)__cvta_generic_to_shared(fsm);
    const uint32_t ksm = qsm + 128 * FP_B;
    const uint32_t vsm = ksm + 2 * FKV_B;

    const int bh = blockIdx.x;
    const int b = bh >> 4, h = bh & 15;
    const int q0 = blockIdx.y << 7;
    const int t = threadIdx.x;
    const int warp = t >> 5, lane = t & 31;
    const int lr = lane >> 2, lc = lane & 3;

    const __half* base  = qkv + (size_t)b * SEQ * (3 * EMBED) + h * HD;
    const __half* kbase = base + EMBED;
    const __half* vbase = base + 2 * EMBED;

    // loaders: Q  -> row t>>1 (0..127), chunks (t&1)*4 .. +3
    //          K/V-> row t>>2 (0..63),  chunks (t&3)*2 .. +1
    const int rq = t >> 1, cq = (t & 1) * 4;
    const int rk = t >> 2, ck = (t & 3) * 2;

    // group 0: Q + K0 + V0
    #pragma unroll
    for (int i = 0; i < 4; i++)
        cp16(qsm + rq * FP_B + (cq + i) * 16,
             base + (size_t)(q0 + rq) * (3 * EMBED) + (cq + i) * 8);
    #pragma unroll
    for (int i = 0; i < 2; i++) {
        cp16(ksm + rk * FP_B + (ck + i) * 16,
             kbase + (size_t)rk * (3 * EMBED) + (ck + i) * 8);
        cp16(vsm + rk * FP_B + (ck + i) * 16,
             vbase + (size_t)rk * (3 * EMBED) + (ck + i) * 8);
    }
    CP_COMMIT();
    // group 1: K1 + V1
    #pragma unroll
    for (int i = 0; i < 2; i++) {
        cp16(ksm + FKV_B + rk * FP_B + (ck + i) * 16,
             kbase + (size_t)(64 + rk) * (3 * EMBED) + (ck + i) * 8);
        cp16(vsm + FKV_B + rk * FP_B + (ck + i) * 16,
             vbase + (size_t)(64 + rk) * (3 * EMBED) + (ck + i) * 8);
    }
    CP_COMMIT();

    float oacc[8][4];
    #pragma unroll
    for (int n = 0; n < 8; n++)
        #pragma unroll
        for (int c = 0; c < 4; c++) oacc[n][c] = 0.f;
    float m0v = -1e30f, m1v = -1e30f, l0v = 0.f, l1v = 0.f;

    const uint32_t qaddr0 = qsm + (uint32_t)(16 * warp + (lane & 15)) * FP_B
                          + (uint32_t)((lane >> 4) << 3) * 2u;
    const int rB  = (lane & 7) + ((lane >> 4) << 3);
    const int khB = ((lane >> 3) & 1) << 3;
    const uint32_t vrow = (uint32_t)(lane & 15);
    const uint32_t voff = (uint32_t)((lane >> 4) << 3) * 2u;

    for (int kt = 0; kt < 16; kt++) {
        if (kt < 15) { CP_WAIT(1); } else { CP_WAIT(0); }
        __syncthreads();
        const uint32_t kb = ksm + (uint32_t)(kt & 1) * FKV_B;
        const uint32_t vb = vsm + (uint32_t)(kt & 1) * FKV_B;

        // ---- S = Q @ K^T ---- (Q pre-scaled by 0.125)
        float sacc[8][4];
        #pragma unroll
        for (int n = 0; n < 8; n++)
            #pragma unroll
            for (int c = 0; c < 4; c++) sacc[n][c] = 0.f;

        #pragma unroll
        for (int kk = 0; kk < 4; kk++) {
            uint32_t a0, a1, a2, a3;
            LDSM4(a0, a1, a2, a3, qaddr0 + (uint32_t)kk * 32u);
            uint32_t bk[8][2];
            #pragma unroll
            for (int np = 0; np < 4; np++) {
                uint32_t addr = kb + (uint32_t)(16 * np + rB) * FP_B
                              + (uint32_t)(16 * kk + khB) * 2u;
                LDSM4(bk[2 * np][0], bk[2 * np][1],
                      bk[2 * np + 1][0], bk[2 * np + 1][1], addr);
            }
            #pragma unroll
            for (int n = 0; n < 8; n++)
                HMMA(sacc[n], a0, a1, a2, a3, bk[n][0], bk[n][1]);
        }

        // ---- online softmax (rows lr and lr+8; a row = 4 lanes via lc) ----
        float mx0 = -1e30f, mx1 = -1e30f;
        #pragma unroll
        for (int n = 0; n < 8; n++) {
            mx0 = fmaxf(mx0, fmaxf(sacc[n][0], sacc[n][1]));
            mx1 = fmaxf(mx1, fmaxf(sacc[n][2], sacc[n][3]));
        }
        mx0 = fmaxf(mx0, __shfl_xor_sync(0xffffffffu, mx0, 1));
        mx0 = fmaxf(mx0, __shfl_xor_sync(0xffffffffu, mx0, 2));
        mx1 = fmaxf(mx1, __shfl_xor_sync(0xffffffffu, mx1, 1));
        mx1 = fmaxf(mx1, __shfl_xor_sync(0xffffffffu, mx1, 2));

        float mn0 = fmaxf(m0v, mx0), mn1 = fmaxf(m1v, mx1);
        float c0 = __expf(m0v - mn0), c1 = __expf(m1v - mn1);

        uint32_t ph[8][2];
        float ls0 = 0.f, ls1 = 0.f;
        #pragma unroll
        for (int n = 0; n < 8; n++) {
            float p0 = __expf(sacc[n][0] - mn0);
            float p1 = __expf(sacc[n][1] - mn0);
            float p2 = __expf(sacc[n][2] - mn1);
            float p3 = __expf(sacc[n][3] - mn1);
            ls0 += p0 + p1;
            ls1 += p2 + p3;
            ph[n][0] = pack2(p0, p1);
            ph[n][1] = pack2(p2, p3);
        }
        ls0 += __shfl_xor_sync(0xffffffffu, ls0, 1);
        ls0 += __shfl_xor_sync(0xffffffffu, ls0, 2);
        ls1 += __shfl_xor_sync(0xffffffffu, ls1, 1);
        ls1 += __shfl_xor_sync(0xffffffffu, ls1, 2);

        l0v = l0v * c0 + ls0;
        l1v = l1v * c1 + ls1;
        m0v = mn0; m1v = mn1;
        #pragma unroll
        for (int n = 0; n < 8; n++) {
            oacc[n][0] *= c0; oacc[n][1] *= c0;
            oacc[n][2] *= c1; oacc[n][3] *= c1;
        }

        // ---- O += P @ V ----
        #pragma unroll
        for (int j = 0; j < 4; j++) {
            uint32_t pa0 = ph[2 * j][0],     pa1 = ph[2 * j][1];
            uint32_t pa2 = ph[2 * j + 1][0], pa3 = ph[2 * j + 1][1];
            #pragma unroll
            for (int np = 0; np < 4; np++) {
                uint32_t v0, v1, v2, v3;
                uint32_t addr = vb + (uint32_t)(16 * j + vrow) * FP_B
                              + (uint32_t)(16 * np) * 2u + voff;
                LDSM4T(v0, v1, v2, v3, addr);
                HMMA(oacc[2 * np],     pa0, pa1, pa2, pa3, v0, v1);
                HMMA(oacc[2 * np + 1], pa0, pa1, pa2, pa3, v2, v3);
            }
        }
        __syncthreads();

        // refill buffer kt&1 with tile kt+2
        if (kt + 2 < 16) {
            uint32_t kd = ksm + (uint32_t)(kt & 1) * FKV_B;
            uint32_t vd = vsm + (uint32_t)(kt & 1) * FKV_B;
            int g0 = (kt + 2) << 6;
            #pragma unroll
            for (int i = 0; i < 2; i++) {
                cp16(kd + rk * FP_B + (ck + i) * 16,
                     kbase + (size_t)(g0 + rk) * (3 * EMBED) + (ck + i) * 8);
                cp16(vd + rk * FP_B + (ck + i) * 16,
                     vbase + (size_t)(g0 + rk) * (3 * EMBED) + (ck + i) * 8);
            }
            CP_COMMIT();
        }
    }

    // ---- epilogue ----
    float inv0 = 1.f / l0v, inv1 = 1.f / l1v;
    int row0 = q0 + 16 * warp + lr;
    __half* o0 = out + (size_t)(b * SEQ + row0) * EMBED + h * HD;
    __half* o1 = o0 + (size_t)8 * EMBED;
    #pragma unroll
    for (int n = 0; n < 8; n++) {
        *reinterpret_cast<__half2*>(o0 + 8 * n + 2 * lc) =
            __floats2half2_rn(oacc[n][0] * inv0, oacc[n][1] * inv0);
        *reinterpret_cast<__half2*>(o1 + 8 * n + 2 * lc) =
            __floats2half2_rn(oacc[n][2] * inv1, oacc[n][3] * inv1);
    }
}

// ---------------- launcher ---------------------------------------------------
extern "C" void kernel_launch(void* const* d_in, const int* in_sizes, int n_in,
                              void* d_out, int out_size)
{
    const float* x      = (const float*)d_in[0];
    const float* ln1_g  = (const float*)d_in[1];
    const float* ln1_b  = (const float*)d_in[2];
    const float* w_qkv  = (const float*)d_in[3];
    const float* b_qkv  = (const float*)d_in[4];
    const float* w_proj = (const float*)d_in[5];
    const float* b_proj = (const float*)d_in[6];
    const float* ln2_g  = (const float*)d_in[7];
    const float* ln2_b  = (const float*)d_in[8];
    const float* w_fc1  = (const float*)d_in[9];
    const float* b_fc1  = (const float*)d_in[10];
    const float* w_fc2  = (const float*)d_in[11];
    const float* b_fc2  = (const float*)d_in[12];
    float* out = (float*)d_out;

    __half *h, *qkv, *attn, *fc1, *wt;
    cudaGetSymbolAddress((void**)&h,    g_h);
    cudaGetSymbolAddress((void**)&qkv,  g_qkv);
    cudaGetSymbolAddress((void**)&attn, g_attn);
    cudaGetSymbolAddress((void**)&fc1,  g_fc1);
    cudaGetSymbolAddress((void**)&wt,   g_wt);

    cudaFuncSetAttribute(tgemm<1>, cudaFuncAttributeMaxDynamicSharedMemorySize, TGEMM_SMEM);
    cudaFuncSetAttribute(tgemm<2>, cudaFuncAttributeMaxDynamicSharedMemorySize, TGEMM_SMEM);
    cudaFuncSetAttribute(tgemm<4>, cudaFuncAttributeMaxDynamicSharedMemorySize, TGEMM_SMEM);
    cudaFuncSetAttribute(flash_mma, cudaFuncAttributeMaxDynamicSharedMemorySize, FLASH_SMEM);

    __half* qkvT  = wt + WT_QKV;
    __half* projT = wt + WT_PROJ;
    __half* fc1T  = wt + WT_FC1;
    __half* fc2T  = wt + WT_FC2;

    // 0) transpose weights to [N, K] fp16 (K-major)
    transpose_kernel<<<dim3(3 * EMBED / 32, EMBED / 32),   dim3(32, 8)>>>(w_qkv,  qkvT,  EMBED,   3 * EMBED);
    transpose_kernel<<<dim3(EMBED / 32,     EMBED / 32),   dim3(32, 8)>>>(w_proj, projT, EMBED,   EMBED);
    transpose_kernel<<<dim3(MLP_DIM / 32,   EMBED / 32),   dim3(32, 8)>>>(w_fc1,  fc1T,  EMBED,   MLP_DIM);
    transpose_kernel<<<dim3(EMBED / 32,     MLP_DIM / 32), dim3(32, 8)>>>(w_fc2,  fc2T,  MLP_DIM, EMBED);

    // 1) LN1: x -> h (fp16)
    ln_kernel<<<ROWS, 256>>>(x, ln1_g, ln1_b, h);

    // 2) QKV GEMM: h @ w_qkv + b_qkv -> qkv (fp16, Q cols x0.125)
    tgemm<4><<<dim3(3 * EMBED / 128, ROWS / 128), 128, TGEMM_SMEM>>>(
        h, qkvT, b_qkv, nullptr, qkv, 3 * EMBED, EMBED);

    // 3) attention -> attn (fp16, tensor cores, Q-tile 128)
    flash_mma<<<dim3(BATCH * HEADS, SEQ / 128), 256, FLASH_SMEM>>>(qkv, attn);

    // 4) proj + residual(x) -> out (fp32)
    tgemm<1><<<dim3(EMBED / 128, ROWS / 128), 128, TGEMM_SMEM>>>(
        attn, projT, b_proj, x, out, EMBED, EMBED);

    // 5) LN2: out -> h (fp16)
    ln_kernel<<<ROWS, 256>>>(out, ln2_g, ln2_b, h);

    // 6) FC1 + GELU: h @ w_fc1 -> fc1 (fp16)
    tgemm<2><<<dim3(MLP_DIM / 128, ROWS / 128), 128, TGEMM_SMEM>>>(
        h, fc1T, b_fc1, nullptr, fc1, MLP_DIM, EMBED);

    // 7) FC2 + residual(out) -> out (fp32, in-place elementwise safe)
    tgemm<1><<<dim3(EMBED / 128, ROWS / 128), 128, TGEMM_SMEM>>>(
        fc1, fc2T, b_fc2, out, out, EMBED, MLP_DIM);
}

// round 14
// speedup vs baseline: 1.0027x; 1.0027x over previous
#include <cuda_runtime.h>
#include <cuda_fp16.h>
#include <math.h>
#include <stdint.h>

#define EMBED 1024
#define HEADS 16
#define HD 64
#define MLP_DIM 4096
#define BATCH 8
#define SEQ 1024
#define ROWS (BATCH * SEQ)   // 8192

// ---------------- scratch (device globals: no allocation allowed) -----------
__device__ __half g_h[ROWS * EMBED];          // 16 MB (LN outputs, fp16)
__device__ __half g_qkv[ROWS * 3 * EMBED];    // 50 MB (fp16, Q pre-scaled)
__device__ __half g_attn[ROWS * EMBED];       // 16 MB (fp16)
__device__ __half g_fc1[ROWS * MLP_DIM];      // 64 MB (fp16)
__device__ __half g_wt[12582912];             // 24 MB (transposed weights, fp16)

#define WT_QKV  0
#define WT_PROJ (3 * EMBED * EMBED)
#define WT_FC1  (WT_PROJ + EMBED * EMBED)
#define WT_FC2  (WT_FC1 + EMBED * MLP_DIM)

__device__ __forceinline__ void cp16(uint32_t dst, const void* src) {
    asm volatile("cp.async.cg.shared.global [%0], [%1], 16;"
                 :: "r"(dst), "l"(src) : "memory");
}
#define CP_COMMIT() asm volatile("cp.async.commit_group;" ::: "memory")
#define CP_WAIT(n)  asm volatile("cp.async.wait_group %0;" :: "n"(n) : "memory")

#define LDSM4(r0, r1, r2, r3, addr) \
    asm volatile("ldmatrix.sync.aligned.m8n8.x4.shared.b16 {%0,%1,%2,%3}, [%4];" \
                 : "=r"(r0), "=r"(r1), "=r"(r2), "=r"(r3) : "r"(addr))
#define LDSM4T(r0, r1, r2, r3, addr) \
    asm volatile("ldmatrix.sync.aligned.m8n8.x4.trans.shared.b16 {%0,%1,%2,%3}, [%4];" \
                 : "=r"(r0), "=r"(r1), "=r"(r2), "=r"(r3) : "r"(addr))

#define HMMA(d, a0, a1, a2, a3, b0, b1) \
    asm volatile("mma.sync.aligned.m16n8k16.row.col.f32.f16.f16.f32 " \
                 "{%0,%1,%2,%3}, {%4,%5,%6,%7}, {%8,%9}, {%0,%1,%2,%3};" \
                 : "+f"((d)[0]), "+f"((d)[1]), "+f"((d)[2]), "+f"((d)[3]) \
                 : "r"(a0), "r"(a1), "r"(a2), "r"(a3), "r"(b0), "r"(b1))

__device__ __forceinline__ uint32_t pack2(float x, float y) {
    __half2 h = __floats2half2_rn(x, y);
    return *reinterpret_cast<uint32_t*>(&h);
}

// ---------------- weight transpose: out[N,K] = fp16(in[K,N]^T) --------------
__global__ __launch_bounds__(256) void transpose_kernel(
    const float* __restrict__ in, __half* __restrict__ out, int K, int N)
{
    __shared__ float tile[32][33];
    int n0 = blockIdx.x * 32, k0 = blockIdx.y * 32;
    int tx = threadIdx.x, ty = threadIdx.y;   // 32 x 8
    #pragma unroll
    for (int i = 0; i < 32; i += 8)
        tile[ty + i][tx] = in[(size_t)(k0 + ty + i) * N + n0 + tx];
    __syncthreads();
    #pragma unroll
    for (int i = 0; i < 32; i += 8)
        out[(size_t)(n0 + ty + i) * K + k0 + tx] = __float2half_rn(tile[tx][ty + i]);
}

// ---------------- fp16 mma.sync GEMM: C = A[M,K] @ WT[N,K]^T ----------------
// CTA 128x128, 4 warps (2M x 2N), warp tile 64x64, m16n8k16 atoms.
// BK=32, 4-stage cp.async pipeline, ONE __syncthreads per slab, loads issued
// before compute each slab.
// MODE 0: +bias -> f32 | MODE 1: +bias+res -> f32 | MODE 2: +bias,GELU -> f16
// MODE 3: +bias -> f16 | MODE 4: +bias, cols<EMBED x0.125 -> f16 (QKV)
#define ROWH   40
#define TILE_B (128 * ROWH * 2)            // 10240 bytes per operand tile
#define NSTAGE 4
#define TGEMM_SMEM (NSTAGE * 2 * TILE_B)   // 81920 bytes

template <int MODE>
__global__ __launch_bounds__(128, 2) void tgemm(
    const __half* __restrict__ A, const __half* __restrict__ WT,
    const float* __restrict__ bias, const float* __restrict__ res,
    void* __restrict__ Cv, int N, int K)
{
    extern __shared__ char smc[];
    const uint32_t smb = (uint32_t)__cvta_generic_to_shared(smc);
    const int t = threadIdx.x;
    const int warp = t >> 5, lane = t & 31;
    const int lr = lane >> 2, lc = lane & 3;
    const int wm = warp >> 1, wn = warp & 1;     // 2 x 2
    const int m0 = blockIdx.y << 7;
    const int n0 = blockIdx.x << 7;

    float acc[4][8][4];
    #pragma unroll
    for (int m = 0; m < 4; m++)
        #pragma unroll
        for (int n = 0; n < 8; n++)
            #pragma unroll
            for (int r = 0; r < 4; r++) acc[m][n][r] = 0.f;

    const __half* Ab = A  + (size_t)m0 * K;
    const __half* Bb = WT + (size_t)n0 * K;
    const int S = K >> 5;

    const int lrow  = t >> 2;    // 0..31
    const int lpart = t & 3;

    const int rA  = lane & 15;
    const int khA = (lane >> 4) << 3;
    const int rB  = (lane & 7) + ((lane >> 4) << 3);
    const int khB = ((lane >> 3) & 1) << 3;

    #define STAGE_LOAD(buf, kc)                                                  \
        do {                                                                     \
            uint32_t sa = smb + (uint32_t)(buf) * (2 * TILE_B);                  \
            uint32_t sb = sa + TILE_B;                                           \
            _Pragma("unroll")                                                    \
            for (int i = 0; i < 4; i++) {                                        \
                int rw = lrow + 32 * i;                                          \
                cp16(sa + rw * 80 + lpart * 16,                                  \
                     Ab + (size_t)rw * K + (kc) + lpart * 8);                    \
                cp16(sb + rw * 80 + lpart * 16,                                  \
                     Bb + (size_t)rw * K + (kc) + lpart * 8);                    \
            }                                                                    \
        } while (0)

    STAGE_LOAD(0, 0);
    CP_COMMIT();
    if (S > 1) { STAGE_LOAD(1, 32); CP_COMMIT(); }
    if (S > 2) { STAGE_LOAD(2, 64); CP_COMMIT(); }

    int buf = 0;
    for (int s = 0; s < S; s++) {
        if (s + 2 < S)      { CP_WAIT(2); }
        else if (s + 1 < S) { CP_WAIT(1); }
        else                { CP_WAIT(0); }
        __syncthreads();

        // Issue next stage load FIRST (target buf+3 == buf-1 mod 4: all reads
        // of it finished before the barrier above), then compute.
        if (s + 3 < S) {
            int nb = buf + 3; if (nb >= NSTAGE) nb -= NSTAGE;
            STAGE_LOAD(nb, (s + 3) << 5);
            CP_COMMIT();
        }

        const uint32_t As = smb + (uint32_t)buf * (2 * TILE_B);
        const uint32_t Bs = As + TILE_B;
        #pragma unroll
        for (int kk = 0; kk < 2; kk++) {
            uint32_t a[4][4], b[8][2];
            #pragma unroll
            for (int m = 0; m < 4; m++) {
                uint32_t addr = As + (uint32_t)(wm * 64 + m * 16 + rA) * 80u
                              + (uint32_t)(kk * 16 + khA) * 2u;
                LDSM4(a[m][0], a[m][1], a[m][2], a[m][3], addr);
            }
            #pragma unroll
            for (int np = 0; np < 4; np++) {
                uint32_t addr = Bs + (uint32_t)(wn * 64 + np * 16 + rB) * 80u
                              + (uint32_t)(kk * 16 + khB) * 2u;
                LDSM4(b[2 * np][0], b[2 * np][1], b[2 * np + 1][0], b[2 * np + 1][1], addr);
            }
            #pragma unroll
            for (int m = 0; m < 4; m++)
                #pragma unroll
                for (int n = 0; n < 8; n++)
                    HMMA(acc[m][n], a[m][0], a[m][1], a[m][2], a[m][3],
                         b[n][0], b[n][1]);
        }
        buf = buf + 1; if (buf == NSTAGE) buf = 0;
    }
    #undef STAGE_LOAD

    // ---------------- epilogue ----------------
    const int rb = m0 + wm * 64;
    const int cb = n0 + wn * 64;
    #pragma unroll
    for (int m = 0; m < 4; m++) {
        #pragma unroll
        for (int n = 0; n < 8; n++) {
            int r = rb + m * 16 + lr;
            int c = cb + n * 8 + lc * 2;
            float2 bv = *reinterpret_cast<const float2*>(bias + c);
            #pragma unroll
            for (int half_ = 0; half_ < 2; half_++) {
                int rr = r + half_ * 8;
                float o0 = acc[m][n][2 * half_ + 0] + bv.x;
                float o1 = acc[m][n][2 * half_ + 1] + bv.y;
                size_t off = (size_t)rr * N + c;
                if (MODE == 1) {
                    float2 rv = *reinterpret_cast<const float2*>(res + off);
                    o0 += rv.x; o1 += rv.y;
                }
                if (MODE == 2) {
                    o0 = 0.5f * o0 * (1.0f + erff(o0 * 0.70710678118654752f));
                    o1 = 0.5f * o1 * (1.0f + erff(o1 * 0.70710678118654752f));
                }
                if (MODE == 4) {
                    float sc = (c < EMBED) ? 0.125f : 1.0f;
                    o0 *= sc; o1 *= sc;
                }
                if (MODE >= 2) {
                    *reinterpret_cast<__half2*>((__half*)Cv + off) =
                        __floats2half2_rn(o0, o1);
                } else {
                    *reinterpret_cast<float2*>((float*)Cv + off) = make_float2(o0, o1);
                }
            }
        }
    }
}

// ---------------- LayerNorm: one block per row (fp16 output) ----------------
__global__ __launch_bounds__(256) void ln_kernel(
    const float* __restrict__ x, const float* __restrict__ g,
    const float* __restrict__ b, __half* __restrict__ out)
{
    int row = blockIdx.x;
    int t = threadIdx.x;
    const float4* xr = reinterpret_cast<const float4*>(x + (size_t)row * EMBED);
    float4 v = xr[t];
    float s  = v.x + v.y + v.z + v.w;
    float ss = v.x * v.x + v.y * v.y + v.z * v.z + v.w * v.w;
    #pragma unroll
    for (int o = 16; o > 0; o >>= 1) {
        s  += __shfl_xor_sync(0xffffffffu, s,  o);
        ss += __shfl_xor_sync(0xffffffffu, ss, o);
    }
    __shared__ float sm[8], sm2[8];
    int w = t >> 5, l = t & 31;
    if (l == 0) { sm[w] = s; sm2[w] = ss; }
    __syncthreads();
    float tot = 0.f, tot2 = 0.f;
    #pragma unroll
    for (int i = 0; i < 8; i++) { tot += sm[i]; tot2 += sm2[i]; }
    float mu   = tot * (1.0f / EMBED);
    float var  = tot2 * (1.0f / EMBED) - mu * mu;
    float rstd = rsqrtf(var + 1e-5f);
    float4 gg = reinterpret_cast<const float4*>(g)[t];
    float4 bb = reinterpret_cast<const float4*>(b)[t];
    __half2* op = reinterpret_cast<__half2*>(out + (size_t)row * EMBED);
    op[2 * t + 0] = __floats2half2_rn((v.x - mu) * rstd * gg.x + bb.x,
                                      (v.y - mu) * rstd * gg.y + bb.y);
    op[2 * t + 1] = __floats2half2_rn((v.z - mu) * rstd * gg.z + bb.z,
                                      (v.w - mu) * rstd * gg.w + bb.w);
}

// ---------------- Flash attention, fp16 tensor cores (R12-proven shape) -----
// grid (B*H, SEQ/64), 128 threads (4 warps x 16 Q rows). KV tiles of 64,
// double-buffered cp.async. Q pre-scaled by 0.125 in the QKV epilogue.
#define FPITCH 72            // halves per smem row
#define FP_B   (FPITCH * 2)  // 144 bytes

__global__ __launch_bounds__(128) void flash_mma(
    const __half* __restrict__ qkv, __half* __restrict__ out)
{
    __shared__ __half Qs[64 * FPITCH];
    __shared__ __half Ks[2][64 * FPITCH];
    __shared__ __half Vs[2][64 * FPITCH];

    const int bh = blockIdx.x;
    const int b = bh >> 4, h = bh & 15;
    const int q0 = blockIdx.y << 6;
    const int t = threadIdx.x;
    const int warp = t >> 5, lane = t & 31;
    const int lr = lane >> 2, lc = lane & 3;

    const __half* base  = qkv + (size_t)b * SEQ * (3 * EMBED) + h * HD;
    const __half* kbase = base + EMBED;
    const __half* vbase = base + 2 * EMBED;

    const int r0 = t >> 3;   // 0..15
    const int cp = t & 7;    // 0..7

    const uint32_t qsm = (uint32_t)__cvta_generic_to_shared(Qs);
    const uint32_t ksm = (uint32_t)__cvta_generic_to_shared(Ks);
    const uint32_t vsm = (uint32_t)__cvta_generic_to_shared(Vs);

    // group 0: Q + K0 + V0
    #pragma unroll
    for (int i = 0; i < 4; i++) {
        int row = r0 + 16 * i;
        cp16(qsm + row * FP_B + cp * 16,
             base  + (size_t)(q0 + row) * (3 * EMBED) + cp * 8);
        cp16(ksm + row * FP_B + cp * 16,
             kbase + (size_t)row * (3 * EMBED) + cp * 8);
        cp16(vsm + row * FP_B + cp * 16,
             vbase + (size_t)row * (3 * EMBED) + cp * 8);
    }
    CP_COMMIT();
    // group 1: K1 + V1
    #pragma unroll
    for (int i = 0; i < 4; i++) {
        int row = r0 + 16 * i;
        cp16(ksm + 64 * FP_B + row * FP_B + cp * 16,
             kbase + (size_t)(64 + row) * (3 * EMBED) + cp * 8);
        cp16(vsm + 64 * FP_B + row * FP_B + cp * 16,
             vbase + (size_t)(64 + row) * (3 * EMBED) + cp * 8);
    }
    CP_COMMIT();

    float oacc[8][4];
    #pragma unroll
    for (int n = 0; n < 8; n++)
        #pragma unroll
        for (int c = 0; c < 4; c++) oacc[n][c] = 0.f;
    float m0v = -1e30f, m1v = -1e30f, l0v = 0.f, l1v = 0.f;

    const uint32_t qaddr0 = qsm + (uint32_t)(16 * warp + (lane & 15)) * FP_B
                          + (uint32_t)((lane >> 4) << 3) * 2u;
    const int rB  = (lane & 7) + ((lane >> 4) << 3);
    const int khB = ((lane >> 3) & 1) << 3;
    const uint32_t vrow = (uint32_t)(lane & 15);
    const uint32_t voff = (uint32_t)((lane >> 4) << 3) * 2u;

    for (int kt = 0; kt < 16; kt++) {
        if (kt < 15) { CP_WAIT(1); } else { CP_WAIT(0); }
        __syncthreads();
        const uint32_t kb = ksm + (uint32_t)(kt & 1) * (64 * FP_B);
        const uint32_t vb = vsm + (uint32_t)(kt & 1) * (64 * FP_B);

        // ---- S = Q @ K^T ---- (Q pre-scaled by 0.125 in QKV epilogue)
        float sacc[8][4];
        #pragma unroll
        for (int n = 0; n < 8; n++)
            #pragma unroll
            for (int c = 0; c < 4; c++) sacc[n][c] = 0.f;

        #pragma unroll
        for (int kk = 0; kk < 4; kk++) {
            uint32_t a0, a1, a2, a3;
            LDSM4(a0, a1, a2, a3, qaddr0 + (uint32_t)kk * 32u);
            uint32_t bk[8][2];
            #pragma unroll
            for (int np = 0; np < 4; np++) {
                uint32_t addr = kb + (uint32_t)(16 * np + rB) * FP_B
                              + (uint32_t)(16 * kk + khB) * 2u;
                LDSM4(bk[2 * np][0], bk[2 * np][1],
                      bk[2 * np + 1][0], bk[2 * np + 1][1], addr);
            }
            #pragma unroll
            for (int n = 0; n < 8; n++)
                HMMA(sacc[n], a0, a1, a2, a3, bk[n][0], bk[n][1]);
        }

        // ---- online softmax (rows lr and lr+8; a row = 4 lanes via lc) ----
        float mx0 = -1e30f, mx1 = -1e30f;
        #pragma unroll
        for (int n = 0; n < 8; n++) {
            mx0 = fmaxf(mx0, fmaxf(sacc[n][0], sacc[n][1]));
            mx1 = fmaxf(mx1, fmaxf(sacc[n][2], sacc[n][3]));
        }
        mx0 = fmaxf(mx0, __shfl_xor_sync(0xffffffffu, mx0, 1));
        mx0 = fmaxf(mx0, __shfl_xor_sync(0xffffffffu, mx0, 2));
        mx1 = fmaxf(mx1, __shfl_xor_sync(0xffffffffu, mx1, 1));
        mx1 = fmaxf(mx1, __shfl_xor_sync(0xffffffffu, mx1, 2));

        float mn0 = fmaxf(m0v, mx0), mn1 = fmaxf(m1v, mx1);
        float c0 = __expf(m0v - mn0), c1 = __expf(m1v - mn1);

        uint32_t ph[8][2];
        float ls0 = 0.f, ls1 = 0.f;
        #pragma unroll
        for (int n = 0; n < 8; n++) {
            float p0 = __expf(sacc[n][0] - mn0);
            float p1 = __expf(sacc[n][1] - mn0);
            float p2 = __expf(sacc[n][2] - mn1);
            float p3 = __expf(sacc[n][3] - mn1);
            ls0 += p0 + p1;
            ls1 += p2 + p3;
            ph[n][0] = pack2(p0, p1);
            ph[n][1] = pack2(p2, p3);
        }
        ls0 += __shfl_xor_sync(0xffffffffu, ls0, 1);
        ls0 += __shfl_xor_sync(0xffffffffu, ls0, 2);
        ls1 += __shfl_xor_sync(0xffffffffu, ls1, 1);
        ls1 += __shfl_xor_sync(0xffffffffu, ls1, 2);

        l0v = l0v * c0 + ls0;
        l1v = l1v * c1 + ls1;
        m0v = mn0; m1v = mn1;
        #pragma unroll
        for (int n = 0; n < 8; n++) {
            oacc[n][0] *= c0; oacc[n][1] *= c0;
            oacc[n][2] *= c1; oacc[n][3] *= c1;
        }

        // ---- O += P @ V ----  (A frags straight from score accumulators)
        #pragma unroll
        for (int j = 0; j < 4; j++) {
            uint32_t pa0 = ph[2 * j][0],     pa1 = ph[2 * j][1];
            uint32_t pa2 = ph[2 * j + 1][0], pa3 = ph[2 * j + 1][1];
            #pragma unroll
            for (int np = 0; np < 4; np++) {
                uint32_t v0, v1, v2, v3;
                uint32_t addr = vb + (uint32_t)(16 * j + vrow) * FP_B
                              + (uint32_t)(16 * np) * 2u + voff;
                LDSM4T(v0, v1, v2, v3, addr);
                HMMA(oacc[2 * np],     pa0, pa1, pa2, pa3, v0, v1);
                HMMA(oacc[2 * np + 1], pa0, pa1, pa2, pa3, v2, v3);
            }
        }
        __syncthreads();

        // refill buffer kt&1 with tile kt+2
        if (kt + 2 < 16) {
            uint32_t kd = ksm + (uint32_t)(kt & 1) * (64 * FP_B);
            uint32_t vd = vsm + (uint32_t)(kt & 1) * (64 * FP_B);
            int g0 = (kt + 2) << 6;
            #pragma unroll
            for (int i = 0; i < 4; i++) {
                int row = r0 + 16 * i;
                cp16(kd + row * FP_B + cp * 16,
                     kbase + (size_t)(g0 + row) * (3 * EMBED) + cp * 8);
                cp16(vd + row * FP_B + cp * 16,
                     vbase + (size_t)(g0 + row) * (3 * EMBED) + cp * 8);
            }
            CP_COMMIT();
        }
    }

    // ---- epilogue ----
    float inv0 = 1.f / l0v, inv1 = 1.f / l1v;
    int row0 = q0 + 16 * warp + lr;
    __half* o0 = out + (size_t)(b * SEQ + row0) * EMBED + h * HD;
    __half* o1 = o0 + (size_t)8 * EMBED;
    #pragma unroll
    for (int n = 0; n < 8; n++) {
        *reinterpret_cast<__half2*>(o0 + 8 * n + 2 * lc) =
            __floats2half2_rn(oacc[n][0] * inv0, oacc[n][1] * inv0);
        *reinterpret_cast<__half2*>(o1 + 8 * n + 2 * lc) =
            __floats2half2_rn(oacc[n][2] * inv1, oacc[n][3] * inv1);
    }
}

// ---------------- launcher ---------------------------------------------------
extern "C" void kernel_launch(void* const* d_in, const int* in_sizes, int n_in,
                              void* d_out, int out_size)
{
    const float* x      = (const float*)d_in[0];
    const float* ln1_g  = (const float*)d_in[1];
    const float* ln1_b  = (const float*)d_in[2];
    const float* w_qkv  = (const float*)d_in[3];
    const float* b_qkv  = (const float*)d_in[4];
    const float* w_proj = (const float*)d_in[5];
    const float* b_proj = (const float*)d_in[6];
    const float* ln2_g  = (const float*)d_in[7];
    const float* ln2_b  = (const float*)d_in[8];
    const float* w_fc1  = (const float*)d_in[9];
    const float* b_fc1  = (const float*)d_in[10];
    const float* w_fc2  = (const float*)d_in[11];
    const float* b_fc2  = (const float*)d_in[12];
    float* out = (float*)d_out;

    __half *h, *qkv, *attn, *fc1, *wt;
    cudaGetSymbolAddress((void**)&h,    g_h);
    cudaGetSymbolAddress((void**)&qkv,  g_qkv);
    cudaGetSymbolAddress((void**)&attn, g_attn);
    cudaGetSymbolAddress((void**)&fc1,  g_fc1);
    cudaGetSymbolAddress((void**)&wt,   g_wt);

    cudaFuncSetAttribute(tgemm<1>, cudaFuncAttributeMaxDynamicSharedMemorySize, TGEMM_SMEM);
    cudaFuncSetAttribute(tgemm<2>, cudaFuncAttributeMaxDynamicSharedMemorySize, TGEMM_SMEM);
    cudaFuncSetAttribute(tgemm<4>, cudaFuncAttributeMaxDynamicSharedMemorySize, TGEMM_SMEM);

    __half* qkvT  = wt + WT_QKV;
    __half* projT = wt + WT_PROJ;
    __half* fc1T  = wt + WT_FC1;
    __half* fc2T  = wt + WT_FC2;

    // 0) transpose weights to [N, K] fp16 (K-major)
    transpose_kernel<<<dim3(3 * EMBED / 32, EMBED / 32),   dim3(32, 8)>>>(w_qkv,  qkvT,  EMBED,   3 * EMBED);
    transpose_kernel<<<dim3(EMBED / 32,     EMBED / 32),   dim3(32, 8)>>>(w_proj, projT, EMBED,   EMBED);
    transpose_kernel<<<dim3(MLP_DIM / 32,   EMBED / 32),   dim3(32, 8)>>>(w_fc1,  fc1T,  EMBED,   MLP_DIM);
    transpose_kernel<<<dim3(EMBED / 32,     MLP_DIM / 32), dim3(32, 8)>>>(w_fc2,  fc2T,  MLP_DIM, EMBED);

    // 1) LN1: x -> h (fp16)
    ln_kernel<<<ROWS, 256>>>(x, ln1_g, ln1_b, h);

    // 2) QKV GEMM: h @ w_qkv + b_qkv -> qkv (fp16, Q cols x0.125)
    tgemm<4><<<dim3(3 * EMBED / 128, ROWS / 128), 128, TGEMM_SMEM>>>(
        h, qkvT, b_qkv, nullptr, qkv, 3 * EMBED, EMBED);

    // 3) attention -> attn (fp16, tensor cores)
    flash_mma<<<dim3(BATCH * HEADS, SEQ / 64), 128>>>(qkv, attn);

    // 4) proj + residual(x) -> out (fp32)
    tgemm<1><<<dim3(EMBED / 128, ROWS / 128), 128, TGEMM_SMEM>>>(
        attn, projT, b_proj, x, out, EMBED, EMBED);

    // 5) LN2: out -> h (fp16)
    ln_kernel<<<ROWS, 256>>>(out, ln2_g, ln2_b, h);

    // 6) FC1 + GELU: h @ w_fc1 -> fc1 (fp16)
    tgemm<2><<<dim3(MLP_DIM / 128, ROWS / 128), 128, TGEMM_SMEM>>>(
        h, fc1T, b_fc1, nullptr, fc1, MLP_DIM, EMBED);

    // 7) FC2 + residual(out) -> out (fp32, in-place elementwise safe)
    tgemm<1><<<dim3(EMBED / 128, ROWS / 128), 128, TGEMM_SMEM>>>(
        fc1, fc2T, b_fc2, out, out, EMBED, MLP_DIM);
}

// round 15
// speedup vs baseline: 1.1030x; 1.1001x over previous
#include <cuda_runtime.h>
#include <cuda_fp16.h>
#include <math.h>
#include <stdint.h>

#define EMBED 1024
#define HEADS 16
#define HD 64
#define MLP_DIM 4096
#define BATCH 8
#define SEQ 1024
#define ROWS (BATCH * SEQ)   // 8192

// ---------------- scratch (device globals: no allocation allowed) -----------
__device__ __half g_h[ROWS * EMBED];          // 16 MB (LN outputs, fp16)
__device__ __half g_qkv[ROWS * 3 * EMBED];    // 50 MB (fp16, Q pre-scaled)
__device__ __half g_attn[ROWS * EMBED];       // 16 MB (fp16)
__device__ __half g_fc1[ROWS * MLP_DIM];      // 64 MB (fp16)
__device__ __half g_wt[12582912];             // 24 MB (transposed weights, fp16)

#define WT_QKV  0
#define WT_PROJ (3 * EMBED * EMBED)
#define WT_FC1  (WT_PROJ + EMBED * EMBED)
#define WT_FC2  (WT_FC1 + EMBED * MLP_DIM)

__device__ __forceinline__ void cp16(uint32_t dst, const void* src) {
    asm volatile("cp.async.cg.shared.global [%0], [%1], 16;"
                 :: "r"(dst), "l"(src) : "memory");
}
#define CP_COMMIT() asm volatile("cp.async.commit_group;" ::: "memory")
#define CP_WAIT(n)  asm volatile("cp.async.wait_group %0;" :: "n"(n) : "memory")

#define LDSM4(r0, r1, r2, r3, addr) \
    asm volatile("ldmatrix.sync.aligned.m8n8.x4.shared.b16 {%0,%1,%2,%3}, [%4];" \
                 : "=r"(r0), "=r"(r1), "=r"(r2), "=r"(r3) : "r"(addr))
#define LDSM4T(r0, r1, r2, r3, addr) \
    asm volatile("ldmatrix.sync.aligned.m8n8.x4.trans.shared.b16 {%0,%1,%2,%3}, [%4];" \
                 : "=r"(r0), "=r"(r1), "=r"(r2), "=r"(r3) : "r"(addr))

#define HMMA(d, a0, a1, a2, a3, b0, b1) \
    asm volatile("mma.sync.aligned.m16n8k16.row.col.f32.f16.f16.f32 " \
                 "{%0,%1,%2,%3}, {%4,%5,%6,%7}, {%8,%9}, {%0,%1,%2,%3};" \
                 : "+f"((d)[0]), "+f"((d)[1]), "+f"((d)[2]), "+f"((d)[3]) \
                 : "r"(a0), "r"(a1), "r"(a2), "r"(a3), "r"(b0), "r"(b1))

__device__ __forceinline__ uint32_t pack2(float x, float y) {
    __half2 h = __floats2half2_rn(x, y);
    return *reinterpret_cast<uint32_t*>(&h);
}

// ---------------- weight transpose: out[N,K] = fp16(in[K,N]^T) --------------
__global__ __launch_bounds__(256) void transpose_kernel(
    const float* __restrict__ in, __half* __restrict__ out, int K, int N)
{
    __shared__ float tile[32][33];
    int n0 = blockIdx.x * 32, k0 = blockIdx.y * 32;
    int tx = threadIdx.x, ty = threadIdx.y;   // 32 x 8
    #pragma unroll
    for (int i = 0; i < 32; i += 8)
        tile[ty + i][tx] = in[(size_t)(k0 + ty + i) * N + n0 + tx];
    __syncthreads();
    #pragma unroll
    for (int i = 0; i < 32; i += 8)
        out[(size_t)(n0 + ty + i) * K + k0 + tx] = __float2half_rn(tile[tx][ty + i]);
}

// ---------------- fp16 mma.sync GEMM: C = A[M,K] @ WT[N,K]^T ----------------
// CTA 128x128, 4 warps (2M x 2N), warp tile 64x64, m16n8k16 atoms.
// BK=32, 4-stage cp.async pipeline, ONE __syncthreads per slab, loads issued
// AFTER compute (R12-measured-best ordering).
// MODE 0: +bias -> f32 | MODE 1: +bias+res -> f32 | MODE 2: +bias,GELU -> f16
// MODE 3: +bias -> f16 | MODE 4: +bias, cols<EMBED x0.125 -> f16 (QKV)
#define ROWH   40
#define TILE_B (128 * ROWH * 2)            // 10240 bytes per operand tile
#define NSTAGE 4
#define TGEMM_SMEM (NSTAGE * 2 * TILE_B)   // 81920 bytes

template <int MODE>
__global__ __launch_bounds__(128, 2) void tgemm(
    const __half* __restrict__ A, const __half* __restrict__ WT,
    const float* __restrict__ bias, const float* __restrict__ res,
    void* __restrict__ Cv, int N, int K)
{
    extern __shared__ char smc[];
    const uint32_t smb = (uint32_t)__cvta_generic_to_shared(smc);
    const int t = threadIdx.x;
    const int warp = t >> 5, lane = t & 31;
    const int lr = lane >> 2, lc = lane & 3;
    const int wm = warp >> 1, wn = warp & 1;     // 2 x 2
    const int m0 = blockIdx.y << 7;
    const int n0 = blockIdx.x << 7;

    float acc[4][8][4];
    #pragma unroll
    for (int m = 0; m < 4; m++)
        #pragma unroll
        for (int n = 0; n < 8; n++)
            #pragma unroll
            for (int r = 0; r < 4; r++) acc[m][n][r] = 0.f;

    const __half* Ab = A  + (size_t)m0 * K;
    const __half* Bb = WT + (size_t)n0 * K;
    const int S = K >> 5;

    const int lrow  = t >> 2;    // 0..31
    const int lpart = t & 3;

    const int rA  = lane & 15;
    const int khA = (lane >> 4) << 3;
    const int rB  = (lane & 7) + ((lane >> 4) << 3);
    const int khB = ((lane >> 3) & 1) << 3;

    #define STAGE_LOAD(buf, kc)                                                  \
        do {                                                                     \
            uint32_t sa = smb + (uint32_t)(buf) * (2 * TILE_B);                  \
            uint32_t sb = sa + TILE_B;                                           \
            _Pragma("unroll")                                                    \
            for (int i = 0; i < 4; i++) {                                        \
                int rw = lrow + 32 * i;                                          \
                cp16(sa + rw * 80 + lpart * 16,                                  \
                     Ab + (size_t)rw * K + (kc) + lpart * 8);                    \
                cp16(sb + rw * 80 + lpart * 16,                                  \
                     Bb + (size_t)rw * K + (kc) + lpart * 8);                    \
            }                                                                    \
        } while (0)

    STAGE_LOAD(0, 0);
    CP_COMMIT();
    if (S > 1) { STAGE_LOAD(1, 32); CP_COMMIT(); }
    if (S > 2) { STAGE_LOAD(2, 64); CP_COMMIT(); }

    int buf = 0;
    for (int s = 0; s < S; s++) {
        if (s + 2 < S)      { CP_WAIT(2); }
        else if (s + 1 < S) { CP_WAIT(1); }
        else                { CP_WAIT(0); }
        __syncthreads();

        const uint32_t As = smb + (uint32_t)buf * (2 * TILE_B);
        const uint32_t Bs = As + TILE_B;
        #pragma unroll
        for (int kk = 0; kk < 2; kk++) {
            uint32_t a[4][4], b[8][2];
            #pragma unroll
            for (int m = 0; m < 4; m++) {
                uint32_t addr = As + (uint32_t)(wm * 64 + m * 16 + rA) * 80u
                              + (uint32_t)(kk * 16 + khA) * 2u;
                LDSM4(a[m][0], a[m][1], a[m][2], a[m][3], addr);
            }
            #pragma unroll
            for (int np = 0; np < 4; np++) {
                uint32_t addr = Bs + (uint32_t)(wn * 64 + np * 16 + rB) * 80u
                              + (uint32_t)(kk * 16 + khB) * 2u;
                LDSM4(b[2 * np][0], b[2 * np][1], b[2 * np + 1][0], b[2 * np + 1][1], addr);
            }
            #pragma unroll
            for (int m = 0; m < 4; m++)
                #pragma unroll
                for (int n = 0; n < 8; n++)
                    HMMA(acc[m][n], a[m][0], a[m][1], a[m][2], a[m][3],
                         b[n][0], b[n][1]);
        }
        // Loads AFTER compute (measured faster in R12 vs load-first in R13/14:
        // cp.async issue traffic otherwise delays the first LDSM/HMMA chain).
        if (s + 3 < S) {
            int nb = buf + 3; if (nb >= NSTAGE) nb -= NSTAGE;
            STAGE_LOAD(nb, (s + 3) << 5);
            CP_COMMIT();
        }
        buf = buf + 1; if (buf == NSTAGE) buf = 0;
    }
    #undef STAGE_LOAD

    // ---------------- epilogue ----------------
    const int rb = m0 + wm * 64;
    const int cb = n0 + wn * 64;
    #pragma unroll
    for (int m = 0; m < 4; m++) {
        #pragma unroll
        for (int n = 0; n < 8; n++) {
            int r = rb + m * 16 + lr;
            int c = cb + n * 8 + lc * 2;
            float2 bv = *reinterpret_cast<const float2*>(bias + c);
            #pragma unroll
            for (int half_ = 0; half_ < 2; half_++) {
                int rr = r + half_ * 8;
                float o0 = acc[m][n][2 * half_ + 0] + bv.x;
                float o1 = acc[m][n][2 * half_ + 1] + bv.y;
                size_t off = (size_t)rr * N + c;
                if (MODE == 1) {
                    float2 rv = *reinterpret_cast<const float2*>(res + off);
                    o0 += rv.x; o1 += rv.y;
                }
                if (MODE == 2) {
                    o0 = 0.5f * o0 * (1.0f + erff(o0 * 0.70710678118654752f));
                    o1 = 0.5f * o1 * (1.0f + erff(o1 * 0.70710678118654752f));
                }
                if (MODE == 4) {
                    float sc = (c < EMBED) ? 0.125f : 1.0f;
                    o0 *= sc; o1 *= sc;
                }
                if (MODE >= 2) {
                    *reinterpret_cast<__half2*>((__half*)Cv + off) =
                        __floats2half2_rn(o0, o1);
                } else {
                    *reinterpret_cast<float2*>((float*)Cv + off) = make_float2(o0, o1);
                }
            }
        }
    }
}

// ---------------- LayerNorm: one block per row (fp16 output) ----------------
__global__ __launch_bounds__(256) void ln_kernel(
    const float* __restrict__ x, const float* __restrict__ g,
    const float* __restrict__ b, __half* __restrict__ out)
{
    int row = blockIdx.x;
    int t = threadIdx.x;
    const float4* xr = reinterpret_cast<const float4*>(x + (size_t)row * EMBED);
    float4 v = xr[t];
    float s  = v.x + v.y + v.z + v.w;
    float ss = v.x * v.x + v.y * v.y + v.z * v.z + v.w * v.w;
    #pragma unroll
    for (int o = 16; o > 0; o >>= 1) {
        s  += __shfl_xor_sync(0xffffffffu, s,  o);
        ss += __shfl_xor_sync(0xffffffffu, ss, o);
    }
    __shared__ float sm[8], sm2[8];
    int w = t >> 5, l = t & 31;
    if (l == 0) { sm[w] = s; sm2[w] = ss; }
    __syncthreads();
    float tot = 0.f, tot2 = 0.f;
    #pragma unroll
    for (int i = 0; i < 8; i++) { tot += sm[i]; tot2 += sm2[i]; }
    float mu   = tot * (1.0f / EMBED);
    float var  = tot2 * (1.0f / EMBED) - mu * mu;
    float rstd = rsqrtf(var + 1e-5f);
    float4 gg = reinterpret_cast<const float4*>(g)[t];
    float4 bb = reinterpret_cast<const float4*>(b)[t];
    __half2* op = reinterpret_cast<__half2*>(out + (size_t)row * EMBED);
    op[2 * t + 0] = __floats2half2_rn((v.x - mu) * rstd * gg.x + bb.x,
                                      (v.y - mu) * rstd * gg.y + bb.y);
    op[2 * t + 1] = __floats2half2_rn((v.z - mu) * rstd * gg.z + bb.z,
                                      (v.w - mu) * rstd * gg.w + bb.w);
}

// ---------------- Flash attention, fp16 tensor cores (R12-proven shape) -----
// grid (B*H, SEQ/64), 128 threads (4 warps x 16 Q rows). KV tiles of 64,
// double-buffered cp.async. Q pre-scaled by 0.125 in the QKV epilogue.
#define FPITCH 72            // halves per smem row
#define FP_B   (FPITCH * 2)  // 144 bytes

__global__ __launch_bounds__(128) void flash_mma(
    const __half* __restrict__ qkv, __half* __restrict__ out)
{
    __shared__ __half Qs[64 * FPITCH];
    __shared__ __half Ks[2][64 * FPITCH];
    __shared__ __half Vs[2][64 * FPITCH];

    const int bh = blockIdx.x;
    const int b = bh >> 4, h = bh & 15;
    const int q0 = blockIdx.y << 6;
    const int t = threadIdx.x;
    const int warp = t >> 5, lane = t & 31;
    const int lr = lane >> 2, lc = lane & 3;

    const __half* base  = qkv + (size_t)b * SEQ * (3 * EMBED) + h * HD;
    const __half* kbase = base + EMBED;
    const __half* vbase = base + 2 * EMBED;

    const int r0 = t >> 3;   // 0..15
    const int cp = t & 7;    // 0..7

    const uint32_t qsm = (uint32_t)__cvta_generic_to_shared(Qs);
    const uint32_t ksm = (uint32_t)__cvta_generic_to_shared(Ks);
    const uint32_t vsm = (uint32_t)__cvta_generic_to_shared(Vs);

    // group 0: Q + K0 + V0
    #pragma unroll
    for (int i = 0; i < 4; i++) {
        int row = r0 + 16 * i;
        cp16(qsm + row * FP_B + cp * 16,
             base  + (size_t)(q0 + row) * (3 * EMBED) + cp * 8);
        cp16(ksm + row * FP_B + cp * 16,
             kbase + (size_t)row * (3 * EMBED) + cp * 8);
        cp16(vsm + row * FP_B + cp * 16,
             vbase + (size_t)row * (3 * EMBED) + cp * 8);
    }
    CP_COMMIT();
    // group 1: K1 + V1
    #pragma unroll
    for (int i = 0; i < 4; i++) {
        int row = r0 + 16 * i;
        cp16(ksm + 64 * FP_B + row * FP_B + cp * 16,
             kbase + (size_t)(64 + row) * (3 * EMBED) + cp * 8);
        cp16(vsm + 64 * FP_B + row * FP_B + cp * 16,
             vbase + (size_t)(64 + row) * (3 * EMBED) + cp * 8);
    }
    CP_COMMIT();

    float oacc[8][4];
    #pragma unroll
    for (int n = 0; n < 8; n++)
        #pragma unroll
        for (int c = 0; c < 4; c++) oacc[n][c] = 0.f;
    float m0v = -1e30f, m1v = -1e30f, l0v = 0.f, l1v = 0.f;

    const uint32_t qaddr0 = qsm + (uint32_t)(16 * warp + (lane & 15)) * FP_B
                          + (uint32_t)((lane >> 4) << 3) * 2u;
    const int rB  = (lane & 7) + ((lane >> 4) << 3);
    const int khB = ((lane >> 3) & 1) << 3;
    const uint32_t vrow = (uint32_t)(lane & 15);
    const uint32_t voff = (uint32_t)((lane >> 4) << 3) * 2u;

    for (int kt = 0; kt < 16; kt++) {
        if (kt < 15) { CP_WAIT(1); } else { CP_WAIT(0); }
        __syncthreads();
        const uint32_t kb = ksm + (uint32_t)(kt & 1) * (64 * FP_B);
        const uint32_t vb = vsm + (uint32_t)(kt & 1) * (64 * FP_B);

        // ---- S = Q @ K^T ---- (Q pre-scaled by 0.125 in QKV epilogue)
        float sacc[8][4];
        #pragma unroll
        for (int n = 0; n < 8; n++)
            #pragma unroll
            for (int c = 0; c < 4; c++) sacc[n][c] = 0.f;

        #pragma unroll
        for (int kk = 0; kk < 4; kk++) {
            uint32_t a0, a1, a2, a3;
            LDSM4(a0, a1, a2, a3, qaddr0 + (uint32_t)kk * 32u);
            uint32_t bk[8][2];
            #pragma unroll
            for (int np = 0; np < 4; np++) {
                uint32_t addr = kb + (uint32_t)(16 * np + rB) * FP_B
                              + (uint32_t)(16 * kk + khB) * 2u;
                LDSM4(bk[2 * np][0], bk[2 * np][1],
                      bk[2 * np + 1][0], bk[2 * np + 1][1], addr);
            }
            #pragma unroll
            for (int n = 0; n < 8; n++)
                HMMA(sacc[n], a0, a1, a2, a3, bk[n][0], bk[n][1]);
        }

        // ---- online softmax (rows lr and lr+8; a row = 4 lanes via lc) ----
        float mx0 = -1e30f, mx1 = -1e30f;
        #pragma unroll
        for (int n = 0; n < 8; n++) {
            mx0 = fmaxf(mx0, fmaxf(sacc[n][0], sacc[n][1]));
            mx1 = fmaxf(mx1, fmaxf(sacc[n][2], sacc[n][3]));
        }
        mx0 = fmaxf(mx0, __shfl_xor_sync(0xffffffffu, mx0, 1));
        mx0 = fmaxf(mx0, __shfl_xor_sync(0xffffffffu, mx0, 2));
        mx1 = fmaxf(mx1, __shfl_xor_sync(0xffffffffu, mx1, 1));
        mx1 = fmaxf(mx1, __shfl_xor_sync(0xffffffffu, mx1, 2));

        float mn0 = fmaxf(m0v, mx0), mn1 = fmaxf(m1v, mx1);
        float c0 = __expf(m0v - mn0), c1 = __expf(m1v - mn1);

        uint32_t ph[8][2];
        float ls0 = 0.f, ls1 = 0.f;
        #pragma unroll
        for (int n = 0; n < 8; n++) {
            float p0 = __expf(sacc[n][0] - mn0);
            float p1 = __expf(sacc[n][1] - mn0);
            float p2 = __expf(sacc[n][2] - mn1);
            float p3 = __expf(sacc[n][3] - mn1);
            ls0 += p0 + p1;
            ls1 += p2 + p3;
            ph[n][0] = pack2(p0, p1);
            ph[n][1] = pack2(p2, p3);
        }
        ls0 += __shfl_xor_sync(0xffffffffu, ls0, 1);
        ls0 += __shfl_xor_sync(0xffffffffu, ls0, 2);
        ls1 += __shfl_xor_sync(0xffffffffu, ls1, 1);
        ls1 += __shfl_xor_sync(0xffffffffu, ls1, 2);

        l0v = l0v * c0 + ls0;
        l1v = l1v * c1 + ls1;
        m0v = mn0; m1v = mn1;
        #pragma unroll
        for (int n = 0; n < 8; n++) {
            oacc[n][0] *= c0; oacc[n][1] *= c0;
            oacc[n][2] *= c1; oacc[n][3] *= c1;
        }

        // ---- O += P @ V ----  (A frags straight from score accumulators)
        #pragma unroll
        for (int j = 0; j < 4; j++) {
            uint32_t pa0 = ph[2 * j][0],     pa1 = ph[2 * j][1];
            uint32_t pa2 = ph[2 * j + 1][0], pa3 = ph[2 * j + 1][1];
            #pragma unroll
            for (int np = 0; np < 4; np++) {
                uint32_t v0, v1, v2, v3;
                uint32_t addr = vb + (uint32_t)(16 * j + vrow) * FP_B
                              + (uint32_t)(16 * np) * 2u + voff;
                LDSM4T(v0, v1, v2, v3, addr);
                HMMA(oacc[2 * np],     pa0, pa1, pa2, pa3, v0, v1);
                HMMA(oacc[2 * np + 1], pa0, pa1, pa2, pa3, v2, v3);
            }
        }
        __syncthreads();

        // refill buffer kt&1 with tile kt+2
        if (kt + 2 < 16) {
            uint32_t kd = ksm + (uint32_t)(kt & 1) * (64 * FP_B);
            uint32_t vd = vsm + (uint32_t)(kt & 1) * (64 * FP_B);
            int g0 = (kt + 2) << 6;
            #pragma unroll
            for (int i = 0; i < 4; i++) {
                int row = r0 + 16 * i;
                cp16(kd + row * FP_B + cp * 16,
                     kbase + (size_t)(g0 + row) * (3 * EMBED) + cp * 8);
                cp16(vd + row * FP_B + cp * 16,
                     vbase + (size_t)(g0 + row) * (3 * EMBED) + cp * 8);
            }
            CP_COMMIT();
        }
    }

    // ---- epilogue ----
    float inv0 = 1.f / l0v, inv1 = 1.f / l1v;
    int row0 = q0 + 16 * warp + lr;
    __half* o0 = out + (size_t)(b * SEQ + row0) * EMBED + h * HD;
    __half* o1 = o0 + (size_t)8 * EMBED;
    #pragma unroll
    for (int n = 0; n < 8; n++) {
        *reinterpret_cast<__half2*>(o0 + 8 * n + 2 * lc) =
            __floats2half2_rn(oacc[n][0] * inv0, oacc[n][1] * inv0);
        *reinterpret_cast<__half2*>(o1 + 8 * n + 2 * lc) =
            __floats2half2_rn(oacc[n][2] * inv1, oacc[n][3] * inv1);
    }
}

// ---------------- launcher ---------------------------------------------------
extern "C" void kernel_launch(void* const* d_in, const int* in_sizes, int n_in,
                              void* d_out, int out_size)
{
    const float* x      = (const float*)d_in[0];
    const float* ln1_g  = (const float*)d_in[1];
    const float* ln1_b  = (const float*)d_in[2];
    const float* w_qkv  = (const float*)d_in[3];
    const float* b_qkv  = (const float*)d_in[4];
    const float* w_proj = (const float*)d_in[5];
    const float* b_proj = (const float*)d_in[6];
    const float* ln2_g  = (const float*)d_in[7];
    const float* ln2_b  = (const float*)d_in[8];
    const float* w_fc1  = (const float*)d_in[9];
    const float* b_fc1  = (const float*)d_in[10];
    const float* w_fc2  = (const float*)d_in[11];
    const float* b_fc2  = (const float*)d_in[12];
    float* out = (float*)d_out;

    __half *h, *qkv, *attn, *fc1, *wt;
    cudaGetSymbolAddress((void**)&h,    g_h);
    cudaGetSymbolAddress((void**)&qkv,  g_qkv);
    cudaGetSymbolAddress((void**)&attn, g_attn);
    cudaGetSymbolAddress((void**)&fc1,  g_fc1);
    cudaGetSymbolAddress((void**)&wt,   g_wt);

    cudaFuncSetAttribute(tgemm<1>, cudaFuncAttributeMaxDynamicSharedMemorySize, TGEMM_SMEM);
    cudaFuncSetAttribute(tgemm<2>, cudaFuncAttributeMaxDynamicSharedMemorySize, TGEMM_SMEM);
    cudaFuncSetAttribute(tgemm<4>, cudaFuncAttributeMaxDynamicSharedMemorySize, TGEMM_SMEM);

    __half* qkvT  = wt + WT_QKV;
    __half* projT = wt + WT_PROJ;
    __half* fc1T  = wt + WT_FC1;
    __half* fc2T  = wt + WT_FC2;

    // 0) transpose weights to [N, K] fp16 (K-major)
    transpose_kernel<<<dim3(3 * EMBED / 32, EMBED / 32),   dim3(32, 8)>>>(w_qkv,  qkvT,  EMBED,   3 * EMBED);
    transpose_kernel<<<dim3(EMBED / 32,     EMBED / 32),   dim3(32, 8)>>>(w_proj, projT, EMBED,   EMBED);
    transpose_kernel<<<dim3(MLP_DIM / 32,   EMBED / 32),   dim3(32, 8)>>>(w_fc1,  fc1T,  EMBED,   MLP_DIM);
    transpose_kernel<<<dim3(EMBED / 32,     MLP_DIM / 32), dim3(32, 8)>>>(w_fc2,  fc2T,  MLP_DIM, EMBED);

    // 1) LN1: x -> h (fp16)
    ln_kernel<<<ROWS, 256>>>(x, ln1_g, ln1_b, h);

    // 2) QKV GEMM: h @ w_qkv + b_qkv -> qkv (fp16, Q cols x0.125)
    tgemm<4><<<dim3(3 * EMBED / 128, ROWS / 128), 128, TGEMM_SMEM>>>(
        h, qkvT, b_qkv, nullptr, qkv, 3 * EMBED, EMBED);

    // 3) attention -> attn (fp16, tensor cores)
    flash_mma<<<dim3(BATCH * HEADS, SEQ / 64), 128>>>(qkv, attn);

    // 4) proj + residual(x) -> out (fp32)
    tgemm<1><<<dim3(EMBED / 128, ROWS / 128), 128, TGEMM_SMEM>>>(
        attn, projT, b_proj, x, out, EMBED, EMBED);

    // 5) LN2: out -> h (fp16)
    ln_kernel<<<ROWS, 256>>>(out, ln2_g, ln2_b, h);

    // 6) FC1 + GELU: h @ w_fc1 -> fc1 (fp16)
    tgemm<2><<<dim3(MLP_DIM / 128, ROWS / 128), 128, TGEMM_SMEM>>>(
        h, fc1T, b_fc1, nullptr, fc1, MLP_DIM, EMBED);

    // 7) FC2 + residual(out) -> out (fp32, in-place elementwise safe)
    tgemm<1><<<dim3(EMBED / 128, ROWS / 128), 128, TGEMM_SMEM>>>(
        fc1, fc2T, b_fc2, out, out, EMBED, MLP_DIM);
}